// round 1
// baseline (speedup 1.0000x reference)
#include <cuda_runtime.h>

// Gray-Scott reaction-diffusion residual.
// Input:  output [50, 2, 100, 100, 100] fp32  (d_in[0])
//         laplace_filter [1,1,5,5,5]          (d_in[1], unused: stencil hardcoded)
// Output: f_u (48,96,96,96) followed by f_v (48,96,96,96), fp32.

#define NZ   100
#define NXY  100
#define SLICE_C  1000000      // 100^3, one channel one timestep
#define STRIDE_T 2000000      // 2 channels per timestep
#define OUTE 96
#define OUTVOL (96*96*96)     // 884736

__global__ void __launch_bounds__(96) gs_residual_kernel(
    const float* __restrict__ in, float* __restrict__ out)
{
    const int z = threadIdx.x;        // 0..95
    const int x = blockIdx.x;         // 0..95
    const int y = blockIdx.y;         // 0..95
    const int t = blockIdx.z;         // 0..47

    // input interior coordinates
    const int idx = (y + 2) * 10000 + (x + 2) * 100 + (z + 2);

    const float* __restrict__ u = in + (long long)t * STRIDE_T;
    const float* __restrict__ v = u + SLICE_C;

    // stencil weights: s = [-1/12, 4/3, -5/2, 4/3, -1/12] on each axis;
    // center contributes 3 * (-5/2) = -7.5
    const float S0 = -1.0f / 12.0f;
    const float S1 = 4.0f / 3.0f;
    const float SC = -7.5f;
    const float DX = 100.0f / 48.0f;
    const float INV_DX2 = 1.0f / (DX * DX);
    const float INV_DT = 1.0f / 0.5f;
    const float DU = 0.2f, DV = 0.1f, FF = 0.025f, KK = 0.055f;

    // ---- u channel ----
    float uc = u[idx];
    float s1u = u[idx - 1] + u[idx + 1]
              + u[idx - 100] + u[idx + 100]
              + u[idx - 10000] + u[idx + 10000];
    float s2u = u[idx - 2] + u[idx + 2]
              + u[idx - 200] + u[idx + 200]
              + u[idx - 20000] + u[idx + 20000];
    float lap_u = (S1 * s1u + S0 * s2u + SC * uc) * INV_DX2;

    // ---- v channel ----
    float vc = v[idx];
    float s1v = v[idx - 1] + v[idx + 1]
              + v[idx - 100] + v[idx + 100]
              + v[idx - 10000] + v[idx + 10000];
    float s2v = v[idx - 2] + v[idx + 2]
              + v[idx - 200] + v[idx + 200]
              + v[idx - 20000] + v[idx + 20000];
    float lap_v = (S1 * s1v + S0 * s2v + SC * vc) * INV_DX2;

    // ---- time derivative (t+1 same spatial point) ----
    float un = u[idx + STRIDE_T];
    float vn = v[idx + STRIDE_T];
    float u_t = (un - uc) * INV_DT;
    float v_t = (vn - vc) * INV_DT;

    float uvv = uc * vc * vc;

    float f_u = DU * lap_u - uvv + FF * (1.0f - uc) - u_t;
    float f_v = DV * lap_v + uvv - (FF + KK) * vc - v_t;

    const int oidx = t * OUTVOL + y * (OUTE * OUTE) + x * OUTE + z;
    out[oidx]               = f_u;
    out[48 * OUTVOL + oidx] = f_v;
}

extern "C" void kernel_launch(void* const* d_in, const int* in_sizes, int n_in,
                              void* d_out, int out_size)
{
    const float* in = (const float*)d_in[0];
    float* out = (float*)d_out;
    dim3 grid(96, 96, 48);
    dim3 block(96, 1, 1);
    gs_residual_kernel<<<grid, block>>>(in, out);
}

// round 3
// speedup vs baseline: 1.1018x; 1.1018x over previous
#include <cuda_runtime.h>

// Gray-Scott reaction-diffusion residual, y-march + float2 vectorized.
// Input:  output [50, 2, 100, 100, 100] fp32  (d_in[0])
// Output: f_u (48,96,96,96) then f_v (48,96,96,96), fp32.

#define SLICE_C  1000000      // 100^3
#define STRIDE_T 2000000      // 2 channels
#define PLANE    10000        // 100*100
#define ROW      100
#define OUTE     96
#define OUTP     (96*96)      // 9216
#define OUTVOL   (96*96*96)   // 884736

__global__ void __launch_bounds__(192) gs_residual_v3(
    const float* __restrict__ in, float* __restrict__ out)
{
    const int zp = threadIdx.x;              // 0..47 (z pair)
    const int z  = zp * 2;                   // output z (even)
    const int x  = blockIdx.x * 4 + threadIdx.y;   // 0..95
    const int t  = blockIdx.y;               // 0..47

    const float* __restrict__ u = in + (long long)t * STRIDE_T;
    const float* __restrict__ v = u + SLICE_C;
    const float* __restrict__ un_p = u + STRIDE_T;   // t+1, channel u
    const float* __restrict__ vn_p = v + STRIDE_T;   // t+1, channel v

    // offset of the center float2 within an input y-plane (covers input z+2, z+3)
    const int base = (x + 2) * ROW + (z + 2);

    const float S0 = -1.0f / 12.0f;
    const float S1 = 4.0f / 3.0f;
    const float SC = -7.5f;
    const float DXv = 100.0f / 48.0f;
    const float INV_DX2 = 1.0f / (DXv * DXv);
    const float INV_DT = 2.0f;               // 1/0.5
    const float DU = 0.2f, DV = 0.1f, FF = 0.025f, KK = 0.055f;

    // register queue of center float2s for input planes y .. y+4
    float2 qu[5], qv[5];
#pragma unroll
    for (int i = 0; i < 4; i++) {
        qu[i] = *(const float2*)(u + i * PLANE + base);
        qv[i] = *(const float2*)(v + i * PLANE + base);
    }

    int oidx = t * OUTVOL + x * OUTE + z;    // output index for yc=0

    for (int yc = 0; yc < 96; yc++) {
        const int pc = (yc + 2) * PLANE + base;   // center plane index

        // new far-plane centers (y+4)
        qu[4] = *(const float2*)(u + (yc + 4) * PLANE + base);
        qv[4] = *(const float2*)(v + (yc + 4) * PLANE + base);

        // z-halo: left = inputs z, z+1 ; right = inputs z+4, z+5
        float2 uzl = *(const float2*)(u + pc - 2);
        float2 uzr = *(const float2*)(u + pc + 2);
        float2 vzl = *(const float2*)(v + pc - 2);
        float2 vzr = *(const float2*)(v + pc + 2);

        // x taps
        float2 uxm1 = *(const float2*)(u + pc - ROW);
        float2 uxp1 = *(const float2*)(u + pc + ROW);
        float2 uxm2 = *(const float2*)(u + pc - 2 * ROW);
        float2 uxp2 = *(const float2*)(u + pc + 2 * ROW);
        float2 vxm1 = *(const float2*)(v + pc - ROW);
        float2 vxp1 = *(const float2*)(v + pc + ROW);
        float2 vxm2 = *(const float2*)(v + pc - 2 * ROW);
        float2 vxp2 = *(const float2*)(v + pc + 2 * ROW);

        // t+1 centers
        float2 unx = *(const float2*)(un_p + pc);
        float2 vnx = *(const float2*)(vn_p + pc);

        float2 uc = qu[2];
        float2 vc = qv[2];

        // ---- u laplacian ----
        // point 0 (input z+2): z±1 = uzl.y, uc.y ; z±2 = uzl.x, uzr.x
        float s1u0 = uzl.y + uc.y + uxm1.x + uxp1.x + qu[1].x + qu[3].x;
        float s2u0 = uzl.x + uzr.x + uxm2.x + uxp2.x + qu[0].x + qu[4].x;
        // point 1 (input z+3): z±1 = uc.x, uzr.x ; z±2 = uzl.y, uzr.y
        float s1u1 = uc.x + uzr.x + uxm1.y + uxp1.y + qu[1].y + qu[3].y;
        float s2u1 = uzl.y + uzr.y + uxm2.y + uxp2.y + qu[0].y + qu[4].y;
        float lapu0 = (S1 * s1u0 + S0 * s2u0 + SC * uc.x) * INV_DX2;
        float lapu1 = (S1 * s1u1 + S0 * s2u1 + SC * uc.y) * INV_DX2;

        // ---- v laplacian ----
        float s1v0 = vzl.y + vc.y + vxm1.x + vxp1.x + qv[1].x + qv[3].x;
        float s2v0 = vzl.x + vzr.x + vxm2.x + vxp2.x + qv[0].x + qv[4].x;
        float s1v1 = vc.x + vzr.x + vxm1.y + vxp1.y + qv[1].y + qv[3].y;
        float s2v1 = vzl.y + vzr.y + vxm2.y + vxp2.y + qv[0].y + qv[4].y;
        float lapv0 = (S1 * s1v0 + S0 * s2v0 + SC * vc.x) * INV_DX2;
        float lapv1 = (S1 * s1v1 + S0 * s2v1 + SC * vc.y) * INV_DX2;

        // ---- reaction + time derivative ----
        float uvv0 = uc.x * vc.x * vc.x;
        float uvv1 = uc.y * vc.y * vc.y;
        float ut0 = (unx.x - uc.x) * INV_DT;
        float ut1 = (unx.y - uc.y) * INV_DT;
        float vt0 = (vnx.x - vc.x) * INV_DT;
        float vt1 = (vnx.y - vc.y) * INV_DT;

        float2 fu, fv;
        fu.x = DU * lapu0 - uvv0 + FF * (1.0f - uc.x) - ut0;
        fu.y = DU * lapu1 - uvv1 + FF * (1.0f - uc.y) - ut1;
        fv.x = DV * lapv0 + uvv0 - (FF + KK) * vc.x - vt0;
        fv.y = DV * lapv1 + uvv1 - (FF + KK) * vc.y - vt1;

        *(float2*)(out + oidx) = fu;
        *(float2*)(out + 48 * OUTVOL + oidx) = fv;
        oidx += OUTP;

        // shift queues
        qu[0] = qu[1]; qu[1] = qu[2]; qu[2] = qu[3]; qu[3] = qu[4];
        qv[0] = qv[1]; qv[1] = qv[2]; qv[2] = qv[3]; qv[3] = qv[4];
    }
}

extern "C" void kernel_launch(void* const* d_in, const int* in_sizes, int n_in,
                              void* d_out, int out_size)
{
    const float* in = (const float*)d_in[0];
    float* out = (float*)d_out;
    dim3 grid(24, 48);       // x-tiles (96/4), t
    dim3 block(48, 4);       // z-pairs, x within tile
    gs_residual_v3<<<grid, block>>>(in, out);
}

// round 4
// speedup vs baseline: 2.0288x; 1.8413x over previous
#include <cuda_runtime.h>

// Gray-Scott reaction-diffusion residual, y-march (chunked) + float2 vectorized.
// Input:  output [50, 2, 100, 100, 100] fp32  (d_in[0])
// Output: f_u (48,96,96,96) then f_v (48,96,96,96), fp32.

#define SLICE_C  1000000      // 100^3
#define STRIDE_T 2000000      // 2 channels
#define PLANE    10000        // 100*100
#define ROW      100
#define OUTE     96
#define OUTP     (96*96)      // 9216
#define OUTVOL   (96*96*96)   // 884736
#define YCHUNK   24           // y steps per block (96/4)

__global__ void __launch_bounds__(192) gs_residual_v4(
    const float* __restrict__ in, float* __restrict__ out)
{
    const int zp = threadIdx.x;                    // 0..47 (z pair)
    const int z  = zp * 2;                         // output z (even)
    const int x  = blockIdx.x * 4 + threadIdx.y;   // 0..95
    const int yb = blockIdx.y * YCHUNK;            // output y chunk start
    const int t  = blockIdx.z;                     // 0..47

    const float* __restrict__ u = in + (long long)t * STRIDE_T;
    const float* __restrict__ v = u + SLICE_C;
    const float* __restrict__ un_p = u + STRIDE_T;   // t+1, channel u
    const float* __restrict__ vn_p = v + STRIDE_T;   // t+1, channel v

    // offset of the center float2 within an input y-plane (covers input z+2, z+3)
    const int base = (x + 2) * ROW + (z + 2);

    const float S0 = -1.0f / 12.0f;
    const float S1 = 4.0f / 3.0f;
    const float SC = -7.5f;
    const float DXv = 100.0f / 48.0f;
    const float INV_DX2 = 1.0f / (DXv * DXv);
    const float INV_DT = 2.0f;               // 1/0.5
    const float DU = 0.2f, DV = 0.1f, FF = 0.025f, KK = 0.055f;

    // register queue of center float2s for input planes yb .. yb+3
    float2 qu[5], qv[5];
#pragma unroll
    for (int i = 0; i < 4; i++) {
        qu[i] = *(const float2*)(u + (yb + i) * PLANE + base);
        qv[i] = *(const float2*)(v + (yb + i) * PLANE + base);
    }

    int oidx = t * OUTVOL + yb * OUTP + x * OUTE + z;   // output index for yc=yb

#pragma unroll 2
    for (int yy = 0; yy < YCHUNK; yy++) {
        const int yc = yb + yy;
        const int pc = (yc + 2) * PLANE + base;   // center plane index

        // new far-plane centers (y+4)
        qu[4] = *(const float2*)(u + (yc + 4) * PLANE + base);
        qv[4] = *(const float2*)(v + (yc + 4) * PLANE + base);

        // z-halo: left = inputs z, z+1 ; right = inputs z+4, z+5
        float2 uzl = *(const float2*)(u + pc - 2);
        float2 uzr = *(const float2*)(u + pc + 2);
        float2 vzl = *(const float2*)(v + pc - 2);
        float2 vzr = *(const float2*)(v + pc + 2);

        // x taps
        float2 uxm1 = *(const float2*)(u + pc - ROW);
        float2 uxp1 = *(const float2*)(u + pc + ROW);
        float2 uxm2 = *(const float2*)(u + pc - 2 * ROW);
        float2 uxp2 = *(const float2*)(u + pc + 2 * ROW);
        float2 vxm1 = *(const float2*)(v + pc - ROW);
        float2 vxp1 = *(const float2*)(v + pc + ROW);
        float2 vxm2 = *(const float2*)(v + pc - 2 * ROW);
        float2 vxp2 = *(const float2*)(v + pc + 2 * ROW);

        // t+1 centers
        float2 unx = *(const float2*)(un_p + pc);
        float2 vnx = *(const float2*)(vn_p + pc);

        float2 uc = qu[2];
        float2 vc = qv[2];

        // ---- u laplacian ----
        // point 0 (input z+2): z±1 = uzl.y, uc.y ; z±2 = uzl.x, uzr.x
        float s1u0 = uzl.y + uc.y + uxm1.x + uxp1.x + qu[1].x + qu[3].x;
        float s2u0 = uzl.x + uzr.x + uxm2.x + uxp2.x + qu[0].x + qu[4].x;
        // point 1 (input z+3): z±1 = uc.x, uzr.x ; z±2 = uzl.y, uzr.y
        float s1u1 = uc.x + uzr.x + uxm1.y + uxp1.y + qu[1].y + qu[3].y;
        float s2u1 = uzl.y + uzr.y + uxm2.y + uxp2.y + qu[0].y + qu[4].y;
        float lapu0 = (S1 * s1u0 + S0 * s2u0 + SC * uc.x) * INV_DX2;
        float lapu1 = (S1 * s1u1 + S0 * s2u1 + SC * uc.y) * INV_DX2;

        // ---- v laplacian ----
        float s1v0 = vzl.y + vc.y + vxm1.x + vxp1.x + qv[1].x + qv[3].x;
        float s2v0 = vzl.x + vzr.x + vxm2.x + vxp2.x + qv[0].x + qv[4].x;
        float s1v1 = vc.x + vzr.x + vxm1.y + vxp1.y + qv[1].y + qv[3].y;
        float s2v1 = vzl.y + vzr.y + vxm2.y + vxp2.y + qv[0].y + qv[4].y;
        float lapv0 = (S1 * s1v0 + S0 * s2v0 + SC * vc.x) * INV_DX2;
        float lapv1 = (S1 * s1v1 + S0 * s2v1 + SC * vc.y) * INV_DX2;

        // ---- reaction + time derivative ----
        float uvv0 = uc.x * vc.x * vc.x;
        float uvv1 = uc.y * vc.y * vc.y;
        float ut0 = (unx.x - uc.x) * INV_DT;
        float ut1 = (unx.y - uc.y) * INV_DT;
        float vt0 = (vnx.x - vc.x) * INV_DT;
        float vt1 = (vnx.y - vc.y) * INV_DT;

        float2 fu, fv;
        fu.x = DU * lapu0 - uvv0 + FF * (1.0f - uc.x) - ut0;
        fu.y = DU * lapu1 - uvv1 + FF * (1.0f - uc.y) - ut1;
        fv.x = DV * lapv0 + uvv0 - (FF + KK) * vc.x - vt0;
        fv.y = DV * lapv1 + uvv1 - (FF + KK) * vc.y - vt1;

        *(float2*)(out + oidx) = fu;
        *(float2*)(out + 48 * OUTVOL + oidx) = fv;
        oidx += OUTP;

        // shift queues
        qu[0] = qu[1]; qu[1] = qu[2]; qu[2] = qu[3]; qu[3] = qu[4];
        qv[0] = qv[1]; qv[1] = qv[2]; qv[2] = qv[3]; qv[3] = qv[4];
    }
}

extern "C" void kernel_launch(void* const* d_in, const int* in_sizes, int n_in,
                              void* d_out, int out_size)
{
    const float* in = (const float*)d_in[0];
    float* out = (float*)d_out;
    dim3 grid(24, 4, 48);    // x-tiles (96/4), y-chunks, t
    dim3 block(48, 4);       // z-pairs, x within tile
    gs_residual_v4<<<grid, block>>>(in, out);
}